// round 2
// baseline (speedup 1.0000x reference)
#include <cuda_runtime.h>
#include <cuda_bf16.h>

// Problem constants (fixed by the bench: Q=512, N=262144, D=768, k=10).
#define D_DIM 768
#define Q_DIM 512
#define N_DIM 262144
#define TOPK  10

// Static device scratch (allocation inside kernel_launch is forbidden; module
// globals are the sanctioned workaround).
__device__ float g_d2[(size_t)Q_DIM * (size_t)N_DIM];  // 512 MB
__device__ float g_xsq[N_DIM];
__device__ float g_qsq[Q_DIM];

// ---------------------------------------------------------------------------
// Row squared-norms: one warp per row, float4 loads.
// ---------------------------------------------------------------------------
__global__ __launch_bounds__(256) void rownorm_kernel(const float* __restrict__ X,
                                                      float* __restrict__ out,
                                                      int nrows) {
    int warp = (blockIdx.x * blockDim.x + threadIdx.x) >> 5;
    int lane = threadIdx.x & 31;
    if (warp >= nrows) return;
    const float4* row = (const float4*)(X + (size_t)warp * D_DIM);
    float s = 0.f;
    // 768 floats = 192 float4; 32 lanes -> 6 iterations
    #pragma unroll
    for (int i = 0; i < D_DIM / 4 / 32; i++) {
        float4 v = row[lane + i * 32];
        s += v.x * v.x + v.y * v.y + v.z * v.z + v.w * v.w;
    }
    #pragma unroll
    for (int o = 16; o > 0; o >>= 1) s += __shfl_down_sync(0xffffffffu, s, o);
    if (lane == 0) out[warp] = s;
}

// ---------------------------------------------------------------------------
// d2 GEMM: C[m,n] = qsq[m] - 2 * dot(Q[m,:], L[n,:]) + xsq[n]
// Classic smem-tiled fp32 NT GEMM. BM=BN=128, BK=16, 256 threads, 8x8/thread.
// ---------------------------------------------------------------------------
#define BM 128
#define BN 128
#define BK 16
#define SPAD 4

__global__ __launch_bounds__(256) void gemm_d2_kernel(const float* __restrict__ Qm,
                                                      const float* __restrict__ Lm) {
    __shared__ float As[BK][BM + SPAD];
    __shared__ float Bs[BK][BN + SPAD];

    const int tid = threadIdx.x;
    const int tx = tid & 15;   // 0..15 -> n direction
    const int ty = tid >> 4;   // 0..15 -> m direction
    const int m0 = blockIdx.y * BM;
    const int n0 = blockIdx.x * BN;

    float acc[8][8];
    #pragma unroll
    for (int i = 0; i < 8; i++)
        #pragma unroll
        for (int j = 0; j < 8; j++) acc[i][j] = 0.f;

    for (int k0 = 0; k0 < D_DIM; k0 += BK) {
        // Load A tile (128 rows x 16 cols) and B tile (128 x 16), transposed
        // into [k][row] layout. 512 float4 per tile / 256 threads = 2 each.
        #pragma unroll
        for (int i = 0; i < 2; i++) {
            int idx = tid + i * 256;
            int row = idx >> 2;          // 0..127
            int c4  = (idx & 3) << 2;    // 0,4,8,12
            float4 va = *(const float4*)(Qm + (size_t)(m0 + row) * D_DIM + k0 + c4);
            As[c4 + 0][row] = va.x;
            As[c4 + 1][row] = va.y;
            As[c4 + 2][row] = va.z;
            As[c4 + 3][row] = va.w;
            float4 vb = *(const float4*)(Lm + (size_t)(n0 + row) * D_DIM + k0 + c4);
            Bs[c4 + 0][row] = vb.x;
            Bs[c4 + 1][row] = vb.y;
            Bs[c4 + 2][row] = vb.z;
            Bs[c4 + 3][row] = vb.w;
        }
        __syncthreads();

        #pragma unroll
        for (int kk = 0; kk < BK; kk++) {
            float a[8], b[8];
            *(float4*)&a[0] = *(const float4*)&As[kk][ty * 8];
            *(float4*)&a[4] = *(const float4*)&As[kk][ty * 8 + 4];
            *(float4*)&b[0] = *(const float4*)&Bs[kk][tx * 8];
            *(float4*)&b[4] = *(const float4*)&Bs[kk][tx * 8 + 4];
            #pragma unroll
            for (int i = 0; i < 8; i++)
                #pragma unroll
                for (int j = 0; j < 8; j++) acc[i][j] += a[i] * b[j];
        }
        __syncthreads();
    }

    // Epilogue: d2 = qsq - 2*cross + xsq, vectorized stores.
    #pragma unroll
    for (int i = 0; i < 8; i++) {
        int m = m0 + ty * 8 + i;
        float qs = g_qsq[m];
        #pragma unroll
        for (int j = 0; j < 8; j += 4) {
            int n = n0 + tx * 8 + j;
            float4 v;
            v.x = qs - 2.f * acc[i][j + 0] + g_xsq[n + 0];
            v.y = qs - 2.f * acc[i][j + 1] + g_xsq[n + 1];
            v.z = qs - 2.f * acc[i][j + 2] + g_xsq[n + 2];
            v.w = qs - 2.f * acc[i][j + 3] + g_xsq[n + 3];
            *(float4*)(g_d2 + (size_t)m * N_DIM + n) = v;
        }
    }
}

// ---------------------------------------------------------------------------
// Per-query top-k. One block (256 threads) per query. Each thread keeps a
// sorted ascending top-10 insertion list, then a block tournament merge
// (ties broken by lower index, matching jax.lax.top_k).
// Output layout: out[0 .. Q*K)           = distances (float)
//                out[Q*K .. 2*Q*K)       = indices (as float)
// ---------------------------------------------------------------------------
__global__ __launch_bounds__(256) void topk_kernel(float* __restrict__ out) {
    const int q = blockIdx.x;
    const int tid = threadIdx.x;
    const float* row = g_d2 + (size_t)q * N_DIM;

    float v[TOPK];
    int   id[TOPK];
    #pragma unroll
    for (int i = 0; i < TOPK; i++) { v[i] = 3.0e38f; id[i] = 0x7fffffff; }

    // Strided scan; per-thread scan order is ascending n, and strict '<' on
    // insert keeps the earlier (lower) index on exact ties.
    for (int n = tid; n < N_DIM; n += 256) {
        float val = row[n];
        if (val < v[TOPK - 1]) {
            int pos = TOPK - 1;
            #pragma unroll
            for (int s = TOPK - 1; s > 0; s--) {
                if (pos == s && val < v[s - 1]) {
                    v[s] = v[s - 1];
                    id[s] = id[s - 1];
                    pos = s - 1;
                }
            }
            v[pos] = val;
            id[pos] = n;
        }
    }

    __shared__ float sv[256];
    __shared__ int   si[256];
    __shared__ int   st[256];

    int p = 0;  // per-thread cursor into its sorted list
    for (int k = 0; k < TOPK; k++) {
        float cv = (p < TOPK) ? v[p] : 3.0e38f;
        int   ci = (p < TOPK) ? id[p] : 0x7fffffff;
        sv[tid] = cv;
        si[tid] = ci;
        st[tid] = tid;
        __syncthreads();
        #pragma unroll
        for (int s = 128; s > 0; s >>= 1) {
            if (tid < s) {
                float v2 = sv[tid + s];
                int   i2 = si[tid + s];
                if (v2 < sv[tid] || (v2 == sv[tid] && i2 < si[tid])) {
                    sv[tid] = v2;
                    si[tid] = i2;
                    st[tid] = st[tid + s];
                }
            }
            __syncthreads();
        }
        float wv = sv[0];
        int   wi = si[0];
        int   wt = st[0];
        if (tid == 0) {
            out[q * TOPK + k] = wv;
            out[(size_t)Q_DIM * TOPK + q * TOPK + k] = (float)wi;
        }
        __syncthreads();           // everyone has read sv[0]/st[0]
        if (tid == wt) p++;        // winner advances its cursor
    }
}

// ---------------------------------------------------------------------------
// Launch
// ---------------------------------------------------------------------------
extern "C" void kernel_launch(void* const* d_in, const int* in_sizes, int n_in,
                              void* d_out, int out_size) {
    (void)in_sizes; (void)n_in; (void)out_size;
    const float* query = (const float*)d_in[0];
    const float* lib   = (const float*)d_in[1];
    float* out = (float*)d_out;

    float *d2_ptr, *xsq_ptr, *qsq_ptr;
    cudaGetSymbolAddress((void**)&d2_ptr,  g_d2);
    cudaGetSymbolAddress((void**)&xsq_ptr, g_xsq);
    cudaGetSymbolAddress((void**)&qsq_ptr, g_qsq);
    (void)d2_ptr;

    // Row norms: 8 warps/block
    rownorm_kernel<<<N_DIM / 8, 256>>>(lib, xsq_ptr, N_DIM);
    rownorm_kernel<<<Q_DIM / 8, 256>>>(query, qsq_ptr, Q_DIM);

    // d2 GEMM
    dim3 grid(N_DIM / BN, Q_DIM / BM);
    gemm_d2_kernel<<<grid, 256>>>(query, lib);

    // top-k
    topk_kernel<<<Q_DIM, 256>>>(out);
}

// round 3
// speedup vs baseline: 2.3572x; 2.3572x over previous
#include <cuda_runtime.h>
#include <cuda_bf16.h>
#include <cuda_fp16.h>
#include <cstdint>

#define D_DIM 768
#define Q_DIM 512
#define N_DIM 262144
#define TOPK  10
#define NCAND 32

// ---------------- static device scratch ----------------
__device__ __nv_bfloat16 g_libbf[(size_t)N_DIM * D_DIM];   // 402 MB
__device__ __nv_bfloat16 g_qbf[(size_t)Q_DIM * D_DIM];
__device__ __half        g_d2h[(size_t)Q_DIM * N_DIM];     // 256 MB
__device__ float g_xsq[N_DIM];
__device__ float g_qsq[Q_DIM];
__device__ int   g_cand[Q_DIM * NCAND];

// ---------------------------------------------------------------------------
// Convert fp32 rows -> bf16, and compute row squared norms. One warp per row.
// ---------------------------------------------------------------------------
__global__ __launch_bounds__(256) void convert_kernel(const float* __restrict__ X,
                                                      __nv_bfloat16* __restrict__ Xb,
                                                      float* __restrict__ sq,
                                                      int nrows) {
    int warp = (blockIdx.x * blockDim.x + threadIdx.x) >> 5;
    int lane = threadIdx.x & 31;
    if (warp >= nrows) return;
    const float4* row = (const float4*)(X + (size_t)warp * D_DIM);
    uint2* outrow = (uint2*)(Xb + (size_t)warp * D_DIM);
    float s = 0.f;
    #pragma unroll
    for (int i = 0; i < D_DIM / 4 / 32; i++) {
        float4 v = row[lane + i * 32];
        s += v.x * v.x + v.y * v.y + v.z * v.z + v.w * v.w;
        __nv_bfloat162 p0 = __floats2bfloat162_rn(v.x, v.y);
        __nv_bfloat162 p1 = __floats2bfloat162_rn(v.z, v.w);
        uint2 o;
        o.x = *(uint32_t*)&p0;
        o.y = *(uint32_t*)&p1;
        outrow[lane + i * 32] = o;
    }
    #pragma unroll
    for (int o = 16; o > 0; o >>= 1) s += __shfl_down_sync(0xffffffffu, s, o);
    if (lane == 0) sq[warp] = s;
}

// ---------------------------------------------------------------------------
// bf16 mma.sync GEMM: d2h[m,n] = half(qsq[m] - 2*dot(Q[m],L[n]) + xsq[n])
// CTA 128x128, BK=32, 8 warps (4m x 2n), warp tile 32x64 (2 x 8 mma tiles).
// Smem pitch 40 bf16 (80B) -> conflict-free direct 32-bit fragment loads.
// ---------------------------------------------------------------------------
#define BM 128
#define BN 128
#define BK 32
#define PITCH 40
#define NK (D_DIM / BK)

__device__ __forceinline__ void cp16(void* smem, const void* gmem) {
    uint32_t s = (uint32_t)__cvta_generic_to_shared(smem);
    asm volatile("cp.async.cg.shared.global [%0], [%1], 16;\n" ::"r"(s), "l"(gmem));
}

__global__ __launch_bounds__(256) void gemm_bf16_kernel(const __nv_bfloat16* __restrict__ Qb,
                                                        const __nv_bfloat16* __restrict__ Lb,
                                                        const float* __restrict__ qsq,
                                                        const float* __restrict__ xsq,
                                                        __half* __restrict__ D2) {
    __shared__ __nv_bfloat16 As[2][BM * PITCH];
    __shared__ __nv_bfloat16 Bs[2][BN * PITCH];

    const int tid = threadIdx.x;
    const int warp = tid >> 5;
    const int lane = tid & 31;
    const int gr = lane >> 2;      // group row 0..7
    const int tg = lane & 3;       // thread-in-group
    const int m0 = blockIdx.y * BM;
    const int n0 = blockIdx.x * BN;
    const int wm = (warp >> 1) * 32;
    const int wn = (warp & 1) * 64;

    float acc[2][8][4];
    #pragma unroll
    for (int i = 0; i < 2; i++)
        #pragma unroll
        for (int j = 0; j < 8; j++)
            #pragma unroll
            for (int c = 0; c < 4; c++) acc[i][j][c] = 0.f;

    // tile loader: 512 x 16B per tile per matrix, 256 threads -> 2 each
    auto load_tile = [&](int buf, int kt) {
        int k0 = kt * BK;
        #pragma unroll
        for (int i = 0; i < 2; i++) {
            int idx = tid + i * 256;
            int r = idx >> 2;
            int c = (idx & 3) * 8;
            cp16(&As[buf][r * PITCH + c], Qb + (size_t)(m0 + r) * D_DIM + k0 + c);
            cp16(&Bs[buf][r * PITCH + c], Lb + (size_t)(n0 + r) * D_DIM + k0 + c);
        }
        asm volatile("cp.async.commit_group;\n");
    };

    load_tile(0, 0);
    int buf = 0;

    for (int kt = 0; kt < NK; kt++) {
        if (kt + 1 < NK) {
            load_tile(buf ^ 1, kt + 1);
            asm volatile("cp.async.wait_group 1;\n");
        } else {
            asm volatile("cp.async.wait_group 0;\n");
        }
        __syncthreads();

        #pragma unroll
        for (int s = 0; s < 2; s++) {
            const int kk = s * 16 + tg * 2;
            uint32_t a[2][4], b[8][2];
            #pragma unroll
            for (int i = 0; i < 2; i++) {
                const __nv_bfloat16* base = &As[buf][(wm + i * 16 + gr) * PITCH + kk];
                a[i][0] = *(const uint32_t*)(base);
                a[i][1] = *(const uint32_t*)(base + 8 * PITCH);
                a[i][2] = *(const uint32_t*)(base + 8);
                a[i][3] = *(const uint32_t*)(base + 8 * PITCH + 8);
            }
            #pragma unroll
            for (int j = 0; j < 8; j++) {
                const __nv_bfloat16* bb = &Bs[buf][(wn + j * 8 + gr) * PITCH + kk];
                b[j][0] = *(const uint32_t*)(bb);
                b[j][1] = *(const uint32_t*)(bb + 8);
            }
            #pragma unroll
            for (int i = 0; i < 2; i++)
                #pragma unroll
                for (int j = 0; j < 8; j++) {
                    asm volatile(
                        "mma.sync.aligned.m16n8k16.row.col.f32.bf16.bf16.f32 "
                        "{%0,%1,%2,%3}, {%4,%5,%6,%7}, {%8,%9}, {%0,%1,%2,%3};\n"
                        : "+f"(acc[i][j][0]), "+f"(acc[i][j][1]),
                          "+f"(acc[i][j][2]), "+f"(acc[i][j][3])
                        : "r"(a[i][0]), "r"(a[i][1]), "r"(a[i][2]), "r"(a[i][3]),
                          "r"(b[j][0]), "r"(b[j][1]));
                }
        }
        __syncthreads();
        buf ^= 1;
    }

    // epilogue: d2 = qsq - 2*cross + xsq, stored as half2
    #pragma unroll
    for (int i = 0; i < 2; i++) {
        int m = m0 + wm + i * 16 + gr;
        float q0 = qsq[m];
        float q1 = qsq[m + 8];
        #pragma unroll
        for (int j = 0; j < 8; j++) {
            int n = n0 + wn + j * 8 + tg * 2;
            float x0 = xsq[n], x1 = xsq[n + 1];
            __half2 h0 = __floats2half2_rn(q0 - 2.f * acc[i][j][0] + x0,
                                           q0 - 2.f * acc[i][j][1] + x1);
            __half2 h1 = __floats2half2_rn(q1 - 2.f * acc[i][j][2] + x0,
                                           q1 - 2.f * acc[i][j][3] + x1);
            *(__half2*)(D2 + (size_t)m * N_DIM + n) = h0;
            *(__half2*)(D2 + (size_t)(m + 8) * N_DIM + n) = h1;
        }
    }
}

// ---------------------------------------------------------------------------
// Candidate selection: per query, top-NCAND smallest approx d2 (indices only).
// One block (256 threads) per query; per-thread top-10 list + tournament.
// ---------------------------------------------------------------------------
#define KLOC 10

__global__ __launch_bounds__(256) void cand_kernel() {
    const int q = blockIdx.x;
    const int tid = threadIdx.x;
    const __half2* row = (const __half2*)(g_d2h + (size_t)q * N_DIM);

    float v[KLOC];
    int   id[KLOC];
    #pragma unroll
    for (int i = 0; i < KLOC; i++) { v[i] = 3.0e38f; id[i] = 0x7fffffff; }

    for (int p = tid; p < N_DIM / 2; p += 256) {
        __half2 hv = row[p];
        float2 fv = __half22float2(hv);
        int n = p * 2;
        #pragma unroll
        for (int e = 0; e < 2; e++) {
            float val = (e == 0) ? fv.x : fv.y;
            if (val < v[KLOC - 1]) {
                int pos = KLOC - 1;
                #pragma unroll
                for (int s = KLOC - 1; s > 0; s--) {
                    if (pos == s && val < v[s - 1]) {
                        v[s] = v[s - 1];
                        id[s] = id[s - 1];
                        pos = s - 1;
                    }
                }
                v[pos] = val;
                id[pos] = n + e;
            }
        }
    }

    __shared__ float sv[256];
    __shared__ int   si[256];
    __shared__ int   st[256];

    int p = 0;
    for (int k = 0; k < NCAND; k++) {
        float cv = (p < KLOC) ? v[p] : 3.0e38f;
        int   ci = (p < KLOC) ? id[p] : 0x7fffffff;
        sv[tid] = cv; si[tid] = ci; st[tid] = tid;
        __syncthreads();
        #pragma unroll
        for (int s = 128; s > 0; s >>= 1) {
            if (tid < s) {
                float v2 = sv[tid + s];
                int   i2 = si[tid + s];
                if (v2 < sv[tid] || (v2 == sv[tid] && i2 < si[tid])) {
                    sv[tid] = v2; si[tid] = i2; st[tid] = st[tid + s];
                }
            }
            __syncthreads();
        }
        if (tid == 0) g_cand[q * NCAND + k] = si[0];
        int wt = st[0];
        __syncthreads();
        if (tid == wt) p++;
    }
}

// ---------------------------------------------------------------------------
// Refine: exact fp32 distances for the 32 candidates, emit sorted top-10.
// One block per query, 8 warps x 4 candidates, then warp-0 rank sort.
// ---------------------------------------------------------------------------
__global__ __launch_bounds__(256) void refine_kernel(const float* __restrict__ Qm,
                                                     const float* __restrict__ Lm,
                                                     float* __restrict__ out) {
    const int q = blockIdx.x;
    const int warp = threadIdx.x >> 5;
    const int lane = threadIdx.x & 31;

    __shared__ float sval[NCAND];
    __shared__ int   sidx[NCAND];

    const float4* qrow = (const float4*)(Qm + (size_t)q * D_DIM);

    for (int c = warp; c < NCAND; c += 8) {
        int n = g_cand[q * NCAND + c];
        const float4* lrow = (const float4*)(Lm + (size_t)n * D_DIM);
        float s = 0.f;
        #pragma unroll
        for (int i = 0; i < D_DIM / 4 / 32; i++) {
            float4 a = qrow[lane + i * 32];
            float4 b = lrow[lane + i * 32];
            s += a.x * b.x + a.y * b.y + a.z * b.z + a.w * b.w;
        }
        #pragma unroll
        for (int o = 16; o > 0; o >>= 1) s += __shfl_down_sync(0xffffffffu, s, o);
        if (lane == 0) {
            sval[c] = g_qsq[q] - 2.f * s + g_xsq[n];
            sidx[c] = n;
        }
    }
    __syncthreads();

    if (warp == 0) {
        float v = sval[lane];
        int   idx = sidx[lane];
        int rank = 0;
        #pragma unroll
        for (int j = 0; j < NCAND; j++) {
            float vj = __shfl_sync(0xffffffffu, v, j);
            int   ij = __shfl_sync(0xffffffffu, idx, j);
            rank += (vj < v) || (vj == v && ij < idx);
        }
        if (rank < TOPK) {
            out[q * TOPK + rank] = v;
            out[(size_t)Q_DIM * TOPK + q * TOPK + rank] = (float)idx;
        }
    }
}

// ---------------------------------------------------------------------------
// Launch
// ---------------------------------------------------------------------------
extern "C" void kernel_launch(void* const* d_in, const int* in_sizes, int n_in,
                              void* d_out, int out_size) {
    (void)in_sizes; (void)n_in; (void)out_size;
    const float* query = (const float*)d_in[0];
    const float* lib   = (const float*)d_in[1];
    float* out = (float*)d_out;

    __nv_bfloat16 *libbf_p, *qbf_p;
    __half* d2_p;
    float *xsq_p, *qsq_p;
    cudaGetSymbolAddress((void**)&libbf_p, g_libbf);
    cudaGetSymbolAddress((void**)&qbf_p,   g_qbf);
    cudaGetSymbolAddress((void**)&d2_p,    g_d2h);
    cudaGetSymbolAddress((void**)&xsq_p,   g_xsq);
    cudaGetSymbolAddress((void**)&qsq_p,   g_qsq);

    convert_kernel<<<N_DIM / 8, 256>>>(lib, libbf_p, xsq_p, N_DIM);
    convert_kernel<<<Q_DIM / 8, 256>>>(query, qbf_p, qsq_p, Q_DIM);

    dim3 grid(N_DIM / BN, Q_DIM / BM);
    gemm_bf16_kernel<<<grid, 256>>>(qbf_p, libbf_p, qsq_p, xsq_p, d2_p);

    cand_kernel<<<Q_DIM, 256>>>();
    refine_kernel<<<Q_DIM, 256>>>(query, lib, out);
}